// round 5
// baseline (speedup 1.0000x reference)
#include <cuda_runtime.h>
#include <cuda_bf16.h>
#include <math.h>
#include <stdint.h>

#define K_COMP 64
#define DDIM   256
#define MU_PAD 264     // bf16/row: 132 words -> ldmatrix rows cover all 32 banks
#define S_STAGES 2

// dynamic smem layout (bytes)
#define SMU_OFF   0
#define SMU_BYTES (K_COMP * MU_PAD * 2)            // 33792
#define SC_OFF    SMU_BYTES                        // 4 float arrays of 64
#define SX_OFF    (SMU_BYTES + 1024)               // 34816
#define SX_STAGE  (128 * 32 * 4)                   // 16384 per stage
#define SMEM_TOTAL (SX_OFF + S_STAGES * SX_STAGE)  // 67584

__device__ __align__(16) __nv_bfloat16 g_mu[K_COMP * DDIM];
__device__ float g_kappa[K_COMP];
__device__ float g_logC[K_COMP];
__device__ float g_la[K_COMP];
__device__ float g_C2[K_COMP];

// ---------------- prep: 32 warps, lane-parallel series + warp-reduced softmax ---------
__global__ void prep_fast(const float* __restrict__ alpha_logit,
                          const float* __restrict__ mu_unnorm,
                          const float* __restrict__ log_kappa) {
    __shared__ float cm[K_COMP];
    __shared__ float sa[K_COMP];
    int tid = threadIdx.x, warp = tid >> 5, lane = tid & 31;
    const float s = 0.5f * (float)DDIM - 1.0f;   // 127

    if (tid < K_COMP) {
        cm[tid] = lgammaf((float)tid + 1.0f) + lgammaf((float)tid + s + 1.0f);
        sa[tid] = alpha_logit[tid];
    }
    __syncthreads();

    float a0 = sa[lane], a1 = sa[lane + 32];
    float amax = fmaxf(a0, a1);
#pragma unroll
    for (int off = 16; off > 0; off >>= 1)
        amax = fmaxf(amax, __shfl_xor_sync(0xffffffffu, amax, off));
    float ae = expf(a0 - amax) + expf(a1 - amax);
#pragma unroll
    for (int off = 16; off > 0; off >>= 1)
        ae += __shfl_xor_sync(0xffffffffu, ae, off);
    float lse_a = amax + logf(ae);

#pragma unroll
    for (int rr = 0; rr < 2; rr++) {
        int k = warp + rr * 32;

        const float4* p = reinterpret_cast<const float4*>(mu_unnorm + (size_t)k * DDIM);
        float4 v1 = p[lane * 2], v2 = p[lane * 2 + 1];
        float sum = v1.x*v1.x + v1.y*v1.y + v1.z*v1.z + v1.w*v1.w
                  + v2.x*v2.x + v2.y*v2.y + v2.z*v2.z + v2.w*v2.w;
#pragma unroll
        for (int off = 16; off > 0; off >>= 1)
            sum += __shfl_xor_sync(0xffffffffu, sum, off);
        float inv = 1.0f / fmaxf(sqrtf(sum), 1e-12f);
        __nv_bfloat162* dst = reinterpret_cast<__nv_bfloat162*>(g_mu + (size_t)k * DDIM);
        dst[lane * 4 + 0] = __float22bfloat162_rn(make_float2(v1.x * inv, v1.y * inv));
        dst[lane * 4 + 1] = __float22bfloat162_rn(make_float2(v1.z * inv, v1.w * inv));
        dst[lane * 4 + 2] = __float22bfloat162_rn(make_float2(v2.x * inv, v2.y * inv));
        dst[lane * 4 + 3] = __float22bfloat162_rn(make_float2(v2.z * inv, v2.w * inv));

        float kappa = expf(log_kappa[k]) + 1e-6f;
        float lk2   = logf(0.5f * kappa);
        float t0 = fmaf(2.0f * lane + s,        lk2, -cm[lane]);
        float t1 = fmaf(2.0f * (lane + 32) + s, lk2, -cm[lane + 32]);
        float tm = fmaxf(t0, t1);
#pragma unroll
        for (int off = 16; off > 0; off >>= 1)
            tm = fmaxf(tm, __shfl_xor_sync(0xffffffffu, tm, off));
        float ts = expf(t0 - tm) + expf(t1 - tm);
#pragma unroll
        for (int off = 16; off > 0; off >>= 1)
            ts += __shfl_xor_sync(0xffffffffu, ts, off);

        if (lane == 0) {
            float lbi  = tm + logf(ts);
            float logC = (float)DDIM * (-0.91893853320467274f) + s * logf(kappa) - lbi;
            float la   = sa[k] - lse_a;
            g_kappa[k] = kappa;
            g_logC[k]  = logC;
            g_la[k]    = la;
            g_C2[k]    = logC + la;
        }
    }
}

// ---------------- fast exp: FFMA-only --------------------------------------------------
__device__ __forceinline__ float fexp(float x) {
    x = fmaxf(x, -87.0f);
    float z = x * 1.4426950408889634f;
    float t = z + 12582912.0f;
    float fi = t - 12582912.0f;
    float f = z - fi;
    int  i  = __float_as_int(t) - 0x4B400000;
    float p = 1.3333558e-3f;
    p = fmaf(p, f, 9.6181291e-3f);
    p = fmaf(p, f, 5.5504109e-2f);
    p = fmaf(p, f, 2.4022651e-1f);
    p = fmaf(p, f, 6.9314718e-1f);
    p = fmaf(p, f, 1.0f);
    return __int_as_float(__float_as_int(p) + (i << 23));
}

__device__ __forceinline__ uint32_t f22bf(float2 v) {
    __nv_bfloat162 b = __float22bfloat162_rn(v);
    return *reinterpret_cast<uint32_t*>(&b);
}

// ---------------- main: cp.async-staged A (coalesced), swizzled LDS, MMA --------------
// x staged per 32-col chunk (128 rows x 128B) into a 2-stage smem ring via cp.async.cg.
// 16B-group swizzle: group j of row r stored at j ^ (r&7) -> consumer LDS.128 hits the
// 4-phase smem floor with perfect balance. mu kept in R4's k-pair-permuted layout so the
// fragment algebra is unchanged.
__global__ void __launch_bounds__(256, 3)
vmf_main(const float* __restrict__ x,
         float* __restrict__ out_llh,
         float* __restrict__ out_lp,
         int N) {
    extern __shared__ char smem[];
    __nv_bfloat16* smu = reinterpret_cast<__nv_bfloat16*>(smem + SMU_OFF);
    float* s_kappa = reinterpret_cast<float*>(smem + SC_OFF);
    float* s_logC  = s_kappa + K_COMP;
    float* s_la    = s_logC + K_COMP;
    float* s_C2    = s_la   + K_COMP;

    int tid = threadIdx.x;
    uint32_t smem_u32 = (uint32_t)__cvta_generic_to_shared(smem);
    uint32_t sx_u32   = smem_u32 + SX_OFF;

    int blockRow0 = blockIdx.x * 128;

    // ---- issue cp.async for chunks 0 and 1 immediately (overlap with mu staging) ----
    int pr = tid >> 3;          // producer row 0..31 step-> +32 per q... see below
    int pj = tid & 7;           // 16B group within 128B row-chunk
#pragma unroll
    for (int c = 0; c < 2; c++) {
        uint32_t sb = sx_u32 + c * SX_STAGE;
#pragma unroll
        for (int q = 0; q < 4; q++) {
            int r = q * 32 + pr;
            uint32_t dst = sb + (uint32_t)((r * 32 + ((pj ^ (r & 7)) << 2)) << 2);
            const float* src = x + (size_t)(blockRow0 + r) * DDIM + c * 32 + pj * 4;
            asm volatile("cp.async.cg.shared.global [%0], [%1], 16;\n"
                         :: "r"(dst), "l"(src));
        }
        asm volatile("cp.async.commit_group;\n");
    }

    // ---- stage mu with k-pair permutation + constants ----
    const uint32_t* gmu32 = reinterpret_cast<const uint32_t*>(g_mu);
    for (int idx = tid; idx < K_COMP * (DDIM / 2); idx += 256) {
        int kk = idx >> 7;
        int dp = idx & 127;
        int i  = dp & 7;
        int srcp = (i < 4) ? (2 * i) : (2 * i - 7);
        int src  = (dp & ~7) | srcp;
        reinterpret_cast<uint32_t*>(smu + (size_t)kk * MU_PAD)[dp] = gmu32[kk * 128 + src];
    }
    if (tid < K_COMP) {
        s_kappa[tid] = g_kappa[tid];
        s_logC[tid]  = g_logC[tid];
        s_la[tid]    = g_la[tid];
        s_C2[tid]    = g_C2[tid];
    }

    int warp = tid >> 5, lane = tid & 31;
    int r  = lane >> 2;        // 0..7
    int cq = (lane & 3) * 2;   // logical col-pair base (epilogue)

    // consumer LDS addressing
    int rl0 = warp * 16 + r;                 // local rows rl0, rl0+8 (same &7)
    int jlo = lane & 3;                      // h*4 + jlo = group
    int rx  = rl0 & 7;
    uint32_t a0_base = sx_u32 + (uint32_t)((rl0 * 32) << 2);
    uint32_t a1_base = sx_u32 + (uint32_t)(((rl0 + 8) * 32) << 2);

    // ldmatrix B lane address (reads permuted smu)
    int li   = lane & 7;
    int csel = (lane >> 3) & 1;
    int tsel = (lane >> 4) & 1;
    uint32_t lm_base = smem_u32 + SMU_OFF
                     + (uint32_t)(((li + tsel * 8) * MU_PAD + csel * 8) * 2);

    float acc[8][4];
#pragma unroll
    for (int t = 0; t < 8; t++)
#pragma unroll
        for (int j = 0; j < 4; j++) acc[t][j] = 0.0f;

#pragma unroll
    for (int c = 0; c < 8; c++) {
        if (c == 7) asm volatile("cp.async.wait_group 0;\n");
        else        asm volatile("cp.async.wait_group 1;\n");
        __syncthreads();

        uint32_t stage = (uint32_t)((c & 1) * SX_STAGE);
#pragma unroll
        for (int h = 0; h < 2; h++) {
            int kk = c * 2 + h;
            int g  = (h * 4 + jlo) ^ rx;
            uint32_t a0addr = a0_base + stage + (uint32_t)(g << 4);
            uint32_t a1addr = a1_base + stage + (uint32_t)(g << 4);
            float4 A0, A1;
            asm volatile("ld.shared.v4.f32 {%0,%1,%2,%3}, [%4];"
                         : "=f"(A0.x), "=f"(A0.y), "=f"(A0.z), "=f"(A0.w) : "r"(a0addr));
            asm volatile("ld.shared.v4.f32 {%0,%1,%2,%3}, [%4];"
                         : "=f"(A1.x), "=f"(A1.y), "=f"(A1.z), "=f"(A1.w) : "r"(a1addr));

            uint32_t fa0 = f22bf(make_float2(A0.x, A0.y));
            uint32_t fa2 = f22bf(make_float2(A0.z, A0.w));
            uint32_t fa1 = f22bf(make_float2(A1.x, A1.y));
            uint32_t fa3 = f22bf(make_float2(A1.z, A1.w));

            uint32_t lmaddr = lm_base + (uint32_t)(kk * 32);
#pragma unroll
            for (int tp = 0; tp < 4; tp++) {
                uint32_t b0, b1, b2, b3;
                asm volatile(
                    "ldmatrix.sync.aligned.m8n8.x4.shared.b16 {%0,%1,%2,%3}, [%4];\n"
                    : "=r"(b0), "=r"(b1), "=r"(b2), "=r"(b3)
                    : "r"(lmaddr + (uint32_t)(tp * 16 * MU_PAD * 2)));
                asm volatile(
                    "mma.sync.aligned.m16n8k16.row.col.f32.bf16.bf16.f32 "
                    "{%0,%1,%2,%3}, {%4,%5,%6,%7}, {%8,%9}, {%0,%1,%2,%3};\n"
                    : "+f"(acc[tp*2][0]), "+f"(acc[tp*2][1]), "+f"(acc[tp*2][2]), "+f"(acc[tp*2][3])
                    : "r"(fa0), "r"(fa1), "r"(fa2), "r"(fa3), "r"(b0), "r"(b1));
                asm volatile(
                    "mma.sync.aligned.m16n8k16.row.col.f32.bf16.bf16.f32 "
                    "{%0,%1,%2,%3}, {%4,%5,%6,%7}, {%8,%9}, {%0,%1,%2,%3};\n"
                    : "+f"(acc[tp*2+1][0]), "+f"(acc[tp*2+1][1]), "+f"(acc[tp*2+1][2]), "+f"(acc[tp*2+1][3])
                    : "r"(fa0), "r"(fa1), "r"(fa2), "r"(fa3), "r"(b2), "r"(b3));
            }
        }
        __syncthreads();

        if (c < 6) {
            int nc = c + 2;
            uint32_t sb = sx_u32 + (uint32_t)((nc & 1) * SX_STAGE);
#pragma unroll
            for (int q = 0; q < 4; q++) {
                int rr2 = q * 32 + pr;
                uint32_t dst = sb + (uint32_t)((rr2 * 32 + ((pj ^ (rr2 & 7)) << 2)) << 2);
                const float* src = x + (size_t)(blockRow0 + rr2) * DDIM + nc * 32 + pj * 4;
                asm volatile("cp.async.cg.shared.global [%0], [%1], 16;\n"
                             :: "r"(dst), "l"(src));
            }
            asm volatile("cp.async.commit_group;\n");
        }
    }

    // ---- epilogue: log_prob + per-row logsumexp ----
    int gr0 = blockRow0 + rl0, gr1 = gr0 + 8;
    float2* lp0 = reinterpret_cast<float2*>(out_lp + (size_t)gr0 * K_COMP);
    float2* lp1 = reinterpret_cast<float2*>(out_lp + (size_t)gr1 * K_COMP);

    float m0 = -1e30f, m1 = -1e30f;
#pragma unroll
    for (int t = 0; t < 8; t++) {
        int cc = t * 8 + cq;
        float k0 = s_kappa[cc], k1 = s_kappa[cc + 1];
        float lc0 = s_logC[cc], lc1 = s_logC[cc + 1];
        float la0 = s_la[cc],   la1 = s_la[cc + 1];
        float lp00 = fmaf(k0, acc[t][0], lc0);
        float lp01 = fmaf(k1, acc[t][1], lc1);
        float lp10 = fmaf(k0, acc[t][2], lc0);
        float lp11 = fmaf(k1, acc[t][3], lc1);
        __stcs(lp0 + (cc >> 1), make_float2(lp00, lp01));
        __stcs(lp1 + (cc >> 1), make_float2(lp10, lp11));
        m0 = fmaxf(m0, fmaxf(lp00 + la0, lp01 + la1));
        m1 = fmaxf(m1, fmaxf(lp10 + la0, lp11 + la1));
    }
    m0 = fmaxf(m0, __shfl_xor_sync(0xffffffffu, m0, 1));
    m0 = fmaxf(m0, __shfl_xor_sync(0xffffffffu, m0, 2));
    m1 = fmaxf(m1, __shfl_xor_sync(0xffffffffu, m1, 1));
    m1 = fmaxf(m1, __shfl_xor_sync(0xffffffffu, m1, 2));

    float s0 = 0.0f, s1 = 0.0f;
#pragma unroll
    for (int t = 0; t < 8; t++) {
        int cc = t * 8 + cq;
        float k0 = s_kappa[cc], k1 = s_kappa[cc + 1];
        float c20 = s_C2[cc],   c21 = s_C2[cc + 1];
        s0 += fexp(fmaf(k0, acc[t][0], c20) - m0);
        s0 += fexp(fmaf(k1, acc[t][1], c21) - m0);
        s1 += fexp(fmaf(k0, acc[t][2], c20) - m1);
        s1 += fexp(fmaf(k1, acc[t][3], c21) - m1);
    }
    s0 += __shfl_xor_sync(0xffffffffu, s0, 1);
    s0 += __shfl_xor_sync(0xffffffffu, s0, 2);
    s1 += __shfl_xor_sync(0xffffffffu, s1, 1);
    s1 += __shfl_xor_sync(0xffffffffu, s1, 2);

    if ((lane & 3) == 0) {
        out_llh[gr0] = m0 + __logf(s0);
        out_llh[gr1] = m1 + __logf(s1);
    }
}

// ---------------- launch -----------------------------------------------------------
extern "C" void kernel_launch(void* const* d_in, const int* in_sizes, int n_in,
                              void* d_out, int out_size) {
    const float* x           = (const float*)d_in[0];
    const float* alpha_logit = (const float*)d_in[1];
    const float* mu_unnorm   = (const float*)d_in[2];
    const float* log_kappa   = (const float*)d_in[3];

    int K = in_sizes[1];            // 64
    int D = in_sizes[2] / K;        // 256
    int N = in_sizes[0] / D;        // 262144
    (void)K; (void)n_in; (void)out_size;

    float* out = (float*)d_out;
    float* llh = out;               // (N,)
    float* lp  = out + (size_t)N;   // (N, K) row-major

    cudaFuncSetAttribute(vmf_main, cudaFuncAttributeMaxDynamicSharedMemorySize, SMEM_TOTAL);

    prep_fast<<<1, 1024>>>(alpha_logit, mu_unnorm, log_kappa);
    vmf_main<<<N / 128, 256, SMEM_TOTAL>>>(x, llh, lp, N);
}